// round 4
// baseline (speedup 1.0000x reference)
#include <cuda_runtime.h>
#include <cub/cub.cuh>
#include <math.h>
#include <float.h>
#include <stdint.h>

// Problem shape (fixed by the dataset)
#define SB 128
#define SV 128000
#define SNV (SB * SV)

// Scan kernel geometry: 1000 threads x 128 contiguous elements = 128000
#define SCAN_T 1000
#define SCAN_E 128

// ---------------------------------------------------------------------------
// Static device scratch (allocation-free rule: __device__ globals)
// ---------------------------------------------------------------------------
__device__ unsigned long long g_keys_a[SNV];   // 131 MB
__device__ unsigned long long g_keys_b[SNV];   // 131 MB
__device__ int                g_vals_a[SNV];   // 65.5 MB
__device__ int                g_vals_b[SNV];   // 65.5 MB
__device__ float              g_fs1[SNV];      // x -> e -> (later) cs, 65.5 MB
__device__ float              g_p[SNV];        // sorted probs (f32), 65.5 MB
__device__ int                g_r2[SB];        // nucleus prefix length (logprobs)
__device__ float              g_S2[SB];        // nucleus mass for renorm
__device__ unsigned long long g_sort_temp[8u * 1024u * 1024u];  // 64 MB CUB temp

// Monotone-descending 32-bit key from a nonnegative float prob.
__device__ __forceinline__ unsigned prob_to_desckey(float p) {
    return ~(__float_as_uint(p) | 0x80000000u);
}
__device__ __forceinline__ float key_to_prob(unsigned long long k) {
    return __uint_as_float((~(unsigned)k) & 0x7FFFFFFFu);
}

// ---------------------------------------------------------------------------
// K1: fused softmax + key build.  One block (1024 thr) per row.
//   pass1: x = logit/T (exact f32 div, matches ref), store to scratch, row max
//   pass2: e = expf(x - M) in place, double-precision sum -> S
//   pass3: p = e * (float)(1/S_d), emit composite sort keys + index vals
// ---------------------------------------------------------------------------
__global__ __launch_bounds__(1024) void k1_softmax_keys(
    const float* __restrict__ logits,
    const float* __restrict__ temps,
    float* __restrict__ fs,
    unsigned long long* __restrict__ keys,
    int* __restrict__ vals) {
    __shared__ float  sf[1024];
    __shared__ double sd[1024];
    const int b = blockIdx.x;
    const int t = threadIdx.x;
    const float T = temps[b];
    const float* row = logits + (size_t)b * SV;
    float* frow = fs + (size_t)b * SV;

    // pass1: x + max
    float m = -FLT_MAX;
    for (int i = t; i < SV; i += 1024) {
        float x = row[i] / T;     // exact f32 division (matches reference x)
        frow[i] = x;
        m = fmaxf(m, x);
    }
    sf[t] = m;
    __syncthreads();
    for (int o = 512; o > 0; o >>= 1) {
        if (t < o) sf[t] = fmaxf(sf[t], sf[t + o]);
        __syncthreads();
    }
    const float M = sf[0];
    __syncthreads();

    // pass2: e + double sum
    double s = 0.0;
    for (int i = t; i < SV; i += 1024) {
        float e = expf(frow[i] - M);
        frow[i] = e;
        s += (double)e;
    }
    sd[t] = s;
    __syncthreads();
    for (int o = 512; o > 0; o >>= 1) {
        if (t < o) sd[t] += sd[t + o];
        __syncthreads();
    }
    const float invf = (float)(1.0 / sd[0]);   // near-true reciprocal of S

    // pass3: keys/vals
    const unsigned long long hi = ((unsigned long long)(unsigned)b) << 32;
    for (int i = t; i < SV; i += 1024) {
        float p = frow[i] * invf;              // <=1.5 ULP from true p
        const size_t idx = (size_t)b * SV + i;
        keys[idx] = hi | (unsigned long long)prob_to_desckey(p);
        vals[idx] = i;
    }
}

// ---------------------------------------------------------------------------
// K2: extract sorted probs into a coalesced f32 array (one pass).
// ---------------------------------------------------------------------------
__global__ void k2_extract_p(const unsigned long long* __restrict__ keys,
                             float* __restrict__ p) {
    const size_t i = (size_t)blockIdx.x * blockDim.x + threadIdx.x;
    if (i < (size_t)SNV) p[i] = key_to_prob(keys[i]);
}

// ---------------------------------------------------------------------------
// K3: per-row double-precision scan + prefix counts + sampling (fused).
// One block of 1000 threads per row; thread t owns elems [t*128, t*128+128).
// float4 I/O keeps sector amplification at 2x.
// ---------------------------------------------------------------------------
__global__ __launch_bounds__(SCAN_T) void k3_scan_sample(
    const float* __restrict__ p,
    const unsigned long long* __restrict__ keys,
    const int* __restrict__ vals,
    const int* __restrict__ topks,
    const float* __restrict__ topps,
    const float* __restrict__ topps2,
    const float* __restrict__ minps,
    const float* __restrict__ u,
    float* __restrict__ cs,
    int* __restrict__ r2o,
    float* __restrict__ S2o,
    float* __restrict__ out) {
    __shared__ double sd[SCAN_T];
    __shared__ int    si[1024];
    __shared__ float  s_f[2];
    __shared__ int    s_i[2];

    const int b = blockIdx.x;
    const int t = threadIdx.x;
    const size_t base = (size_t)b * SV;
    const float4* prow4 = (const float4*)(p + base);
    float4* cs4 = (float4*)(cs + base);
    const int q0 = t * (SCAN_E / 4);   // float4 index of my segment start

    // --- phase 1: local double sum of my 128 contiguous elements ---
    double loc = 0.0;
#pragma unroll
    for (int j = 0; j < SCAN_E / 4; j++) {
        float4 v = prow4[q0 + j];
        loc += (double)v.x; loc += (double)v.y; loc += (double)v.z; loc += (double)v.w;
    }
    sd[t] = loc;
    __syncthreads();
    // Hillis-Steele inclusive scan over 1000 doubles
    for (int o = 1; o < SCAN_T; o <<= 1) {
        double a = (t >= o) ? sd[t - o] : 0.0;
        __syncthreads();
        sd[t] += a;
        __syncthreads();
    }
    double run = (t > 0) ? sd[t - 1] : 0.0;   // exclusive offset (near-true)

    // --- phase 2: emit f32 cs, count filter prefixes ---
    const float p1 = topps[b];
    const float p2 = topps2[b];
    const float thr = key_to_prob(keys[base]) * minps[b];  // ps[0] * min_p, f32

    int c1 = 0, c2 = 0, cm = 0;
    float csf_prev = (float)run;   // == cs[r-1] == (cs - ps) for current rank
#pragma unroll
    for (int j = 0; j < SCAN_E / 4; j++) {
        float4 v = prow4[q0 + j];
        float4 o4;
        c1 += (csf_prev <= p1); c2 += (csf_prev <= p2); cm += (v.x >= thr);
        run += (double)v.x; o4.x = (float)run; csf_prev = o4.x;
        c1 += (csf_prev <= p1); c2 += (csf_prev <= p2); cm += (v.y >= thr);
        run += (double)v.y; o4.y = (float)run; csf_prev = o4.y;
        c1 += (csf_prev <= p1); c2 += (csf_prev <= p2); cm += (v.z >= thr);
        run += (double)v.z; o4.z = (float)run; csf_prev = o4.z;
        c1 += (csf_prev <= p1); c2 += (csf_prev <= p2); cm += (v.w >= thr);
        run += (double)v.w; o4.w = (float)run; csf_prev = o4.w;
        cs4[q0 + j] = o4;
    }

    // --- reduce the three prefix counters ---
    si[t] = c1; if (t < 1024 - SCAN_T) si[SCAN_T + t] = 0;
    __syncthreads();
    for (int o = 512; o > 0; o >>= 1) { if (t < o) si[t] += si[t + o]; __syncthreads(); }
    const int rp1 = si[0];
    __syncthreads();
    si[t] = c2; if (t < 1024 - SCAN_T) si[SCAN_T + t] = 0;
    __syncthreads();
    for (int o = 512; o > 0; o >>= 1) { if (t < o) si[t] += si[t + o]; __syncthreads(); }
    const int r2v = si[0];
    __syncthreads();
    si[t] = cm; if (t < 1024 - SCAN_T) si[SCAN_T + t] = 0;
    __syncthreads();
    for (int o = 512; o > 0; o >>= 1) { if (t < o) si[t] += si[t + o]; __syncthreads(); }
    const int rminp = si[0];
    __syncthreads();

    if (t == 0) {
        int k = topks[b];
        if (k > SV) k = SV;
        if (k < 1) k = 1;
        int rf = min(min(k, rp1), rminp);
        if (rf < 1) rf = 1;
        const float total = cs[base + rf - 1];
        s_f[0] = u[b] * total;   // target
        s_i[0] = rf;
        s_i[1] = (r2v < 1) ? 1 : r2v;
    }
    __syncthreads();
    const int rf = s_i[0];
    const float target = s_f[0];

    // --- phase 3: count cs < target over ranks < rf ---
    int cnt = 0;
#pragma unroll
    for (int j = 0; j < SCAN_E / 4; j++) {
        float4 v = cs4[q0 + j];
        const int idx = (q0 + j) * 4;
        cnt += (idx + 0 < rf && v.x < target);
        cnt += (idx + 1 < rf && v.y < target);
        cnt += (idx + 2 < rf && v.z < target);
        cnt += (idx + 3 < rf && v.w < target);
    }
    si[t] = cnt; if (t < 1024 - SCAN_T) si[SCAN_T + t] = 0;
    __syncthreads();
    for (int o = 512; o > 0; o >>= 1) { if (t < o) si[t] += si[t + o]; __syncthreads(); }

    if (t == 0) {
        int s = si[0];
        if (s > SV - 1) s = SV - 1;
        if (s < 0) s = 0;
        const int r2f = s_i[1];
        const int tok = vals[base + s];
        const float ps = p[base + s];
        const float S2 = cs[base + r2f - 1];
        out[b] = (float)tok;                                  // token_ids
        float nlp = (s < r2f) ? fmaxf(logf(ps / S2), -FLT_MAX) : -FLT_MAX;
        out[(size_t)SB + (size_t)SB * SV + b] = nlp;          // next_token_logprobs
        r2o[b] = r2f;
        S2o[b] = S2;
    }
}

// ---------------------------------------------------------------------------
// K4: scatter logprobs.  Every sorted rank writes exactly one output element.
// ---------------------------------------------------------------------------
__global__ void k4_scatter(const float* __restrict__ p,
                           const int* __restrict__ vals,
                           const int* __restrict__ r2o,
                           const float* __restrict__ S2o,
                           float* __restrict__ out) {
    const int b = blockIdx.y;
    const int r = blockIdx.x * blockDim.x + threadIdx.x;
    if (r >= SV) return;
    const size_t pos = (size_t)b * SV + r;
    float val = -FLT_MAX;
    if (r < r2o[b]) {
        val = fmaxf(logf(p[pos] / S2o[b]), -FLT_MAX);
    }
    out[(size_t)SB + (size_t)b * SV + vals[pos]] = val;
}

// ---------------------------------------------------------------------------
// Host launcher (graph-capturable)
// ---------------------------------------------------------------------------
extern "C" void kernel_launch(void* const* d_in, const int* in_sizes, int n_in,
                              void* d_out, int out_size) {
    const float* logits = (const float*)d_in[0];
    const float* temps  = (const float*)d_in[1];
    const int*   topks  = (const int*)d_in[2];
    const float* topps  = (const float*)d_in[3];
    const float* topps2 = (const float*)d_in[4];
    const float* minps  = (const float*)d_in[5];
    const float* u      = (const float*)d_in[6];
    float* out = (float*)d_out;

    void *ka, *kb, *va, *vb, *fs1, *pp, *r2p, *s2p, *tmp;
    cudaGetSymbolAddress(&ka, g_keys_a);
    cudaGetSymbolAddress(&kb, g_keys_b);
    cudaGetSymbolAddress(&va, g_vals_a);
    cudaGetSymbolAddress(&vb, g_vals_b);
    cudaGetSymbolAddress(&fs1, g_fs1);
    cudaGetSymbolAddress(&pp, g_p);
    cudaGetSymbolAddress(&r2p, g_r2);
    cudaGetSymbolAddress(&s2p, g_S2);
    cudaGetSymbolAddress(&tmp, g_sort_temp);

    cudaStream_t stream = 0;

    // K1: fused softmax + keys
    k1_softmax_keys<<<SB, 1024, 0, stream>>>(logits, temps, (float*)fs1,
                                             (unsigned long long*)ka, (int*)va);

    // Sort: single unsegmented stable radix sort on composite keys, bits [0,40)
    cub::DoubleBuffer<unsigned long long> dkeys((unsigned long long*)ka,
                                                (unsigned long long*)kb);
    cub::DoubleBuffer<int> dvals((int*)va, (int*)vb);
    size_t temp_bytes = 0;
    cub::DeviceRadixSort::SortPairs(nullptr, temp_bytes, dkeys, dvals,
                                    SNV, 0, 40, stream);
    if (temp_bytes > sizeof(g_sort_temp)) temp_bytes = sizeof(g_sort_temp);
    cub::DeviceRadixSort::SortPairs(tmp, temp_bytes, dkeys, dvals,
                                    SNV, 0, 40, stream);

    const unsigned long long* skeys = dkeys.Current();
    const int* svals = dvals.Current();

    // K2: sorted probs -> coalesced f32 array
    k2_extract_p<<<(SNV + 511) / 512, 512, 0, stream>>>(skeys, (float*)pp);

    // K3: double-precision scan + prefix counts + sampling (fs1 reused as cs)
    k3_scan_sample<<<SB, SCAN_T, 0, stream>>>((const float*)pp, skeys, svals,
                                              topks, topps, topps2, minps, u,
                                              (float*)fs1, (int*)r2p, (float*)s2p, out);

    // K4: scatter full logprob matrix
    {
        dim3 grid(SV / 256, SB);
        k4_scatter<<<grid, 256, 0, stream>>>((const float*)pp, svals,
                                             (const int*)r2p, (const float*)s2p, out);
    }
}

// round 5
// speedup vs baseline: 1.0003x; 1.0003x over previous
#include <cuda_runtime.h>
#include <cub/cub.cuh>
#include <math.h>
#include <float.h>
#include <stdint.h>

// Problem shape (fixed by the dataset)
#define SB 128
#define SV 128000
#define SNV (SB * SV)

// Scan kernel geometry: 1000 threads x 128 contiguous elements = 128000
#define SCAN_T 1000
#define SCAN_E 128

// ---------------------------------------------------------------------------
// Static device scratch (allocation-free rule: __device__ globals)
// ---------------------------------------------------------------------------
__device__ unsigned long long g_keys_a[SNV];   // 131 MB
__device__ unsigned long long g_keys_b[SNV];   // 131 MB
__device__ int                g_vals_a[SNV];   // 65.5 MB
__device__ int                g_vals_b[SNV];   // 65.5 MB
__device__ float              g_fs1[SNV];      // x -> e -> (later) cs, 65.5 MB
__device__ float              g_p[SNV];        // sorted probs (f32), 65.5 MB
__device__ int                g_r2[SB];        // nucleus prefix length (logprobs)
__device__ float              g_S2[SB];        // nucleus mass for renorm
__device__ unsigned long long g_sort_temp[8u * 1024u * 1024u];  // 64 MB CUB temp

// Monotone-descending 32-bit key from a nonnegative float prob.
__device__ __forceinline__ unsigned prob_to_desckey(float p) {
    return ~(__float_as_uint(p) | 0x80000000u);
}
__device__ __forceinline__ float key_to_prob(unsigned long long k) {
    return __uint_as_float((~(unsigned)k) & 0x7FFFFFFFu);
}

// ---------------------------------------------------------------------------
// K1: fused softmax + key build.  One block (1024 thr) per row.
//   pass1: x = logit/T (exact f32 div, matches ref), store to scratch, row max
//   pass2: e = expf(x - M) in place, double-precision sum -> S
//   pass3: p = e * (float)(1/S_d), emit composite sort keys + index vals
// ---------------------------------------------------------------------------
__global__ __launch_bounds__(1024) void k1_softmax_keys(
    const float* __restrict__ logits,
    const float* __restrict__ temps,
    float* __restrict__ fs,
    unsigned long long* __restrict__ keys,
    int* __restrict__ vals) {
    __shared__ float  sf[1024];
    __shared__ double sd[1024];
    const int b = blockIdx.x;
    const int t = threadIdx.x;
    const float T = temps[b];
    const float* row = logits + (size_t)b * SV;
    float* frow = fs + (size_t)b * SV;

    // pass1: x + max
    float m = -FLT_MAX;
    for (int i = t; i < SV; i += 1024) {
        float x = row[i] / T;     // exact f32 division (matches reference x)
        frow[i] = x;
        m = fmaxf(m, x);
    }
    sf[t] = m;
    __syncthreads();
    for (int o = 512; o > 0; o >>= 1) {
        if (t < o) sf[t] = fmaxf(sf[t], sf[t + o]);
        __syncthreads();
    }
    const float M = sf[0];
    __syncthreads();

    // pass2: e + double sum
    double s = 0.0;
    for (int i = t; i < SV; i += 1024) {
        float e = expf(frow[i] - M);
        frow[i] = e;
        s += (double)e;
    }
    sd[t] = s;
    __syncthreads();
    for (int o = 512; o > 0; o >>= 1) {
        if (t < o) sd[t] += sd[t + o];
        __syncthreads();
    }
    const float invf = (float)(1.0 / sd[0]);   // near-true reciprocal of S

    // pass3: keys/vals
    const unsigned long long hi = ((unsigned long long)(unsigned)b) << 32;
    for (int i = t; i < SV; i += 1024) {
        float p = frow[i] * invf;              // <=1.5 ULP from true p
        const size_t idx = (size_t)b * SV + i;
        keys[idx] = hi | (unsigned long long)prob_to_desckey(p);
        vals[idx] = i;
    }
}

// ---------------------------------------------------------------------------
// K2: extract sorted probs into a coalesced f32 array (one pass).
// ---------------------------------------------------------------------------
__global__ void k2_extract_p(const unsigned long long* __restrict__ keys,
                             float* __restrict__ p) {
    const size_t i = (size_t)blockIdx.x * blockDim.x + threadIdx.x;
    if (i < (size_t)SNV) p[i] = key_to_prob(keys[i]);
}

// ---------------------------------------------------------------------------
// K3: per-row double-precision scan + prefix counts + sampling (fused).
// One block of 1000 threads per row; thread t owns elems [t*128, t*128+128).
// float4 I/O keeps sector amplification at 2x.
// ---------------------------------------------------------------------------
__global__ __launch_bounds__(SCAN_T) void k3_scan_sample(
    const float* __restrict__ p,
    const unsigned long long* __restrict__ keys,
    const int* __restrict__ vals,
    const int* __restrict__ topks,
    const float* __restrict__ topps,
    const float* __restrict__ topps2,
    const float* __restrict__ minps,
    const float* __restrict__ u,
    float* __restrict__ cs,
    int* __restrict__ r2o,
    float* __restrict__ S2o,
    float* __restrict__ out) {
    __shared__ double sd[SCAN_T];
    __shared__ int    si[1024];
    __shared__ float  s_f[2];
    __shared__ int    s_i[2];

    const int b = blockIdx.x;
    const int t = threadIdx.x;
    const size_t base = (size_t)b * SV;
    const float4* prow4 = (const float4*)(p + base);
    float4* cs4 = (float4*)(cs + base);
    const int q0 = t * (SCAN_E / 4);   // float4 index of my segment start

    // --- phase 1: local double sum of my 128 contiguous elements ---
    double loc = 0.0;
#pragma unroll
    for (int j = 0; j < SCAN_E / 4; j++) {
        float4 v = prow4[q0 + j];
        loc += (double)v.x; loc += (double)v.y; loc += (double)v.z; loc += (double)v.w;
    }
    sd[t] = loc;
    __syncthreads();
    // Hillis-Steele inclusive scan over 1000 doubles
    for (int o = 1; o < SCAN_T; o <<= 1) {
        double a = (t >= o) ? sd[t - o] : 0.0;
        __syncthreads();
        sd[t] += a;
        __syncthreads();
    }
    double run = (t > 0) ? sd[t - 1] : 0.0;   // exclusive offset (near-true)

    // --- phase 2: emit f32 cs, count filter prefixes ---
    const float p1 = topps[b];
    const float p2 = topps2[b];
    const float thr = key_to_prob(keys[base]) * minps[b];  // ps[0] * min_p, f32

    int c1 = 0, c2 = 0, cm = 0;
    float csf_prev = (float)run;   // == cs[r-1] == (cs - ps) for current rank
#pragma unroll
    for (int j = 0; j < SCAN_E / 4; j++) {
        float4 v = prow4[q0 + j];
        float4 o4;
        c1 += (csf_prev <= p1); c2 += (csf_prev <= p2); cm += (v.x >= thr);
        run += (double)v.x; o4.x = (float)run; csf_prev = o4.x;
        c1 += (csf_prev <= p1); c2 += (csf_prev <= p2); cm += (v.y >= thr);
        run += (double)v.y; o4.y = (float)run; csf_prev = o4.y;
        c1 += (csf_prev <= p1); c2 += (csf_prev <= p2); cm += (v.z >= thr);
        run += (double)v.z; o4.z = (float)run; csf_prev = o4.z;
        c1 += (csf_prev <= p1); c2 += (csf_prev <= p2); cm += (v.w >= thr);
        run += (double)v.w; o4.w = (float)run; csf_prev = o4.w;
        cs4[q0 + j] = o4;
    }

    // --- reduce the three prefix counters ---
    si[t] = c1; if (t < 1024 - SCAN_T) si[SCAN_T + t] = 0;
    __syncthreads();
    for (int o = 512; o > 0; o >>= 1) { if (t < o) si[t] += si[t + o]; __syncthreads(); }
    const int rp1 = si[0];
    __syncthreads();
    si[t] = c2; if (t < 1024 - SCAN_T) si[SCAN_T + t] = 0;
    __syncthreads();
    for (int o = 512; o > 0; o >>= 1) { if (t < o) si[t] += si[t + o]; __syncthreads(); }
    const int r2v = si[0];
    __syncthreads();
    si[t] = cm; if (t < 1024 - SCAN_T) si[SCAN_T + t] = 0;
    __syncthreads();
    for (int o = 512; o > 0; o >>= 1) { if (t < o) si[t] += si[t + o]; __syncthreads(); }
    const int rminp = si[0];
    __syncthreads();

    if (t == 0) {
        int k = topks[b];
        if (k > SV) k = SV;
        if (k < 1) k = 1;
        int rf = min(min(k, rp1), rminp);
        if (rf < 1) rf = 1;
        const float total = cs[base + rf - 1];
        s_f[0] = u[b] * total;   // target
        s_i[0] = rf;
        s_i[1] = (r2v < 1) ? 1 : r2v;
    }
    __syncthreads();
    const int rf = s_i[0];
    const float target = s_f[0];

    // --- phase 3: count cs < target over ranks < rf ---
    int cnt = 0;
#pragma unroll
    for (int j = 0; j < SCAN_E / 4; j++) {
        float4 v = cs4[q0 + j];
        const int idx = (q0 + j) * 4;
        cnt += (idx + 0 < rf && v.x < target);
        cnt += (idx + 1 < rf && v.y < target);
        cnt += (idx + 2 < rf && v.z < target);
        cnt += (idx + 3 < rf && v.w < target);
    }
    si[t] = cnt; if (t < 1024 - SCAN_T) si[SCAN_T + t] = 0;
    __syncthreads();
    for (int o = 512; o > 0; o >>= 1) { if (t < o) si[t] += si[t + o]; __syncthreads(); }

    if (t == 0) {
        int s = si[0];
        if (s > SV - 1) s = SV - 1;
        if (s < 0) s = 0;
        const int r2f = s_i[1];
        const int tok = vals[base + s];
        const float ps = p[base + s];
        const float S2 = cs[base + r2f - 1];
        out[b] = (float)tok;                                  // token_ids
        float nlp = (s < r2f) ? fmaxf(logf(ps / S2), -FLT_MAX) : -FLT_MAX;
        out[(size_t)SB + (size_t)SB * SV + b] = nlp;          // next_token_logprobs
        r2o[b] = r2f;
        S2o[b] = S2;
    }
}

// ---------------------------------------------------------------------------
// K4: scatter logprobs.  Every sorted rank writes exactly one output element.
// ---------------------------------------------------------------------------
__global__ void k4_scatter(const float* __restrict__ p,
                           const int* __restrict__ vals,
                           const int* __restrict__ r2o,
                           const float* __restrict__ S2o,
                           float* __restrict__ out) {
    const int b = blockIdx.y;
    const int r = blockIdx.x * blockDim.x + threadIdx.x;
    if (r >= SV) return;
    const size_t pos = (size_t)b * SV + r;
    float val = -FLT_MAX;
    if (r < r2o[b]) {
        val = fmaxf(logf(p[pos] / S2o[b]), -FLT_MAX);
    }
    out[(size_t)SB + (size_t)b * SV + vals[pos]] = val;
}

// ---------------------------------------------------------------------------
// Host launcher (graph-capturable)
// ---------------------------------------------------------------------------
extern "C" void kernel_launch(void* const* d_in, const int* in_sizes, int n_in,
                              void* d_out, int out_size) {
    const float* logits = (const float*)d_in[0];
    const float* temps  = (const float*)d_in[1];
    const int*   topks  = (const int*)d_in[2];
    const float* topps  = (const float*)d_in[3];
    const float* topps2 = (const float*)d_in[4];
    const float* minps  = (const float*)d_in[5];
    const float* u      = (const float*)d_in[6];
    float* out = (float*)d_out;

    void *ka, *kb, *va, *vb, *fs1, *pp, *r2p, *s2p, *tmp;
    cudaGetSymbolAddress(&ka, g_keys_a);
    cudaGetSymbolAddress(&kb, g_keys_b);
    cudaGetSymbolAddress(&va, g_vals_a);
    cudaGetSymbolAddress(&vb, g_vals_b);
    cudaGetSymbolAddress(&fs1, g_fs1);
    cudaGetSymbolAddress(&pp, g_p);
    cudaGetSymbolAddress(&r2p, g_r2);
    cudaGetSymbolAddress(&s2p, g_S2);
    cudaGetSymbolAddress(&tmp, g_sort_temp);

    cudaStream_t stream = 0;

    // K1: fused softmax + keys
    k1_softmax_keys<<<SB, 1024, 0, stream>>>(logits, temps, (float*)fs1,
                                             (unsigned long long*)ka, (int*)va);

    // Sort: single unsegmented stable radix sort on composite keys, bits [0,40)
    cub::DoubleBuffer<unsigned long long> dkeys((unsigned long long*)ka,
                                                (unsigned long long*)kb);
    cub::DoubleBuffer<int> dvals((int*)va, (int*)vb);
    size_t temp_bytes = 0;
    cub::DeviceRadixSort::SortPairs(nullptr, temp_bytes, dkeys, dvals,
                                    SNV, 0, 40, stream);
    if (temp_bytes > sizeof(g_sort_temp)) temp_bytes = sizeof(g_sort_temp);
    cub::DeviceRadixSort::SortPairs(tmp, temp_bytes, dkeys, dvals,
                                    SNV, 0, 40, stream);

    const unsigned long long* skeys = dkeys.Current();
    const int* svals = dvals.Current();

    // K2: sorted probs -> coalesced f32 array
    k2_extract_p<<<(SNV + 511) / 512, 512, 0, stream>>>(skeys, (float*)pp);

    // K3: double-precision scan + prefix counts + sampling (fs1 reused as cs)
    k3_scan_sample<<<SB, SCAN_T, 0, stream>>>((const float*)pp, skeys, svals,
                                              topks, topps, topps2, minps, u,
                                              (float*)fs1, (int*)r2p, (float*)s2p, out);

    // K4: scatter full logprob matrix
    {
        dim3 grid(SV / 256, SB);
        k4_scatter<<<grid, 256, 0, stream>>>((const float*)pp, svals,
                                             (const int*)r2p, (const float*)s2p, out);
    }
}

// round 6
// speedup vs baseline: 2.8150x; 2.8142x over previous
#include <cuda_runtime.h>
#include <cub/block/block_radix_sort.cuh>
#include <math.h>
#include <float.h>
#include <limits.h>
#include <stdint.h>

#define SB 128
#define SV 128000
#define HCAP 8192          // per-row gather capacity (head / crossing bucket)
#define HEADN 2048         // head size needed (top_ks <= 2047)
typedef unsigned long long ull;

// ---------------------------------------------------------------------------
// Static device scratch (allocation-free rule)
// ---------------------------------------------------------------------------
__device__ float  g_work[(size_t)SB * SV];   // e = exp(x - M), 65.5 MB
__device__ ull    g_head[(size_t)SB * HCAP]; // head candidates (8.4 MB)
__device__ ull    g_b2buf[(size_t)SB * HCAP];// crossing-bucket elems (8.4 MB)
__device__ float  g_invf[SB];                // 1/S (f32)  == ps[0]
__device__ float  g_S2f[SB];                 // nucleus mass (f32)
__device__ double g_cm2[SB];                 // exact mass strictly above bucket
__device__ int    g_cab[SB];                 // count strictly above bucket
__device__ int    g_B2[SB];                  // crossing bucket id
__device__ int    g_hcnt[SB];
__device__ int    g_bcnt[SB];
__device__ ull    g_kstar[SB];               // largest member key (nucleus)

// key48: ascending sort order == p descending, index ascending (stable argsort)
__device__ __forceinline__ ull make_key(unsigned pb, int idx) {
    return (((ull)(0x7FFFFFFFu - pb)) << 17) | (unsigned)idx;
}
__device__ __forceinline__ float key_p(ull k) {
    return __uint_as_float(0x7FFFFFFFu - (unsigned)(k >> 17));
}
__device__ __forceinline__ int key_idx(ull k) { return (int)(k & 0x1FFFFull); }

// ---------------------------------------------------------------------------
// K1: per-row softmax + exact packed histogram + bucket select + gather.
// One block of 1024 threads per row.
// ---------------------------------------------------------------------------
__global__ __launch_bounds__(1024) void k1_kernel(
    const float* __restrict__ logits,
    const float* __restrict__ temps,
    const float* __restrict__ topps2) {
    __shared__ ull    sh_hist[1024];
    __shared__ double sh_d[1024];
    __shared__ int    sh_i[1024];
    __shared__ float  sh_f[1024];
    __shared__ int    s_B2, s_minb, s_Bk, s_cab, s_hc, s_bc;
    __shared__ double s_cm2;

    const int b = blockIdx.x;
    const int t = threadIdx.x;
    const float T = temps[b];
    const float* row = logits + (size_t)b * SV;
    float* erow = g_work + (size_t)b * SV;

    sh_hist[t] = 0ull;
    if (t == 0) { s_B2 = -1; s_minb = 1024; s_hc = 0; s_bc = 0; }

    // pass 1: row max of x = l/T (exact f32 division, matching reference)
    float m = -FLT_MAX;
    for (int i = t; i < SV; i += 1024) m = fmaxf(m, row[i] / T);
    sh_f[t] = m;
    __syncthreads();
    for (int o = 512; o > 0; o >>= 1) {
        if (t < o) sh_f[t] = fmaxf(sh_f[t], sh_f[t + o]);
        __syncthreads();
    }
    const float M = sh_f[0];

    // pass 2: e = expf(x - M) -> g_work; double sum
    double s = 0.0;
    for (int i = t; i < SV; i += 1024) {
        float e = expf(row[i] / T - M);
        erow[i] = e;
        s += (double)e;
    }
    sh_d[t] = s;
    __syncthreads();
    for (int o = 512; o > 0; o >>= 1) {
        if (t < o) sh_d[t] += sh_d[t + o];
        __syncthreads();
    }
    const float invf = (float)(1.0 / sh_d[0]);
    if (t == 0) g_invf[b] = invf;
    __syncthreads();

    // pass 3: exact packed histogram: one ull atomic per element.
    //   bucket = pbits>>20 (single exponent per bucket); packed = count<<42 | sig24
    for (int i = t; i < SV; i += 1024) {
        unsigned pb = __float_as_uint(erow[i] * invf);
        if (pb) {
            unsigned sig = (pb & 0x7FFFFFu) | 0x800000u;
            atomicAdd(&sh_hist[pb >> 20], (1ull << 42) | (ull)sig);
        }
    }
    __syncthreads();

    // bucket stats (exact): count + mass = sig_sum * 2^(e-150)
    const ull h = sh_hist[t];
    const int cnt = (int)(h >> 42);
    const double mass = ldexp((double)(h & ((1ull << 42) - 1ull)), (int)(t >> 3) - 150);

    // suffix (descending-p) inclusive scans of count and mass
    sh_i[t] = cnt; sh_d[t] = mass;
    __syncthreads();
    for (int o = 1; o < 1024; o <<= 1) {
        int iv = 0; double dv = 0.0;
        if (t + o < 1024) { iv = sh_i[t + o]; dv = sh_d[t + o]; }
        __syncthreads();
        sh_i[t] += iv; sh_d[t] += dv;
        __syncthreads();
    }
    const double p2d = (double)topps2[b];
    const int    ccincl = sh_i[t];
    const double cmincl = sh_d[t];
    const int    ccnext = (t < 1023) ? sh_i[t + 1] : 0;
    const double cmnext = (t < 1023) ? sh_d[t + 1] : 0.0;

    // head threshold bucket: highest b with suffix count >= HEADN (unique)
    if (ccincl >= HEADN && ccnext < HEADN) s_Bk = t;
    // nucleus crossing bucket: cm_above <= p2 < cm_incl (unique; mass>0)
    if (cnt > 0) {
        atomicMin(&s_minb, t);
        if (cmnext <= p2d && cmincl > p2d) { s_B2 = t; s_cm2 = cmnext; s_cab = ccnext; }
    }
    __syncthreads();
    if (s_B2 < 0 && t == s_minb) { s_B2 = t; s_cm2 = cmnext; s_cab = ccnext; }
    __syncthreads();
    const int B2 = s_B2, Bk = s_Bk;
    if (t == 0) { g_B2[b] = B2; g_cm2[b] = s_cm2; g_cab[b] = s_cab; }

    // pass 4: gather head candidates + crossing-bucket elements
    const unsigned thk  = ((unsigned)Bk) << 20;
    const unsigned b2lo = ((unsigned)B2) << 20;
    const unsigned b2hi = b2lo + (1u << 20);
    for (int i = t; i < SV; i += 1024) {
        unsigned pb = __float_as_uint(erow[i] * invf);
        if (pb >= thk) {
            int pos = atomicAdd(&s_hc, 1);
            if (pos < HCAP) g_head[(size_t)b * HCAP + pos] = make_key(pb, i);
        }
        if (pb >= b2lo && pb < b2hi) {
            int pos = atomicAdd(&s_bc, 1);
            if (pos < HCAP) g_b2buf[(size_t)b * HCAP + pos] = make_key(pb, i);
        }
    }
    __syncthreads();
    if (t == 0) { g_hcnt[b] = min(s_hc, HCAP); g_bcnt[b] = min(s_bc, HCAP); }
}

// ---------------------------------------------------------------------------
// Block sorter: 512 threads x 16 items = 8192 keys, 48-bit
// ---------------------------------------------------------------------------
typedef cub::BlockRadixSort<ull, 512, 16> Sorter512;

// ---------------------------------------------------------------------------
// K2b: sort crossing bucket, walk f32 boundary test, emit Kstar + S2.
// ---------------------------------------------------------------------------
__global__ __launch_bounds__(512) void k2b_kernel(const float* __restrict__ topps2) {
    extern __shared__ char dynsm[];
    __shared__ double sd[512];
    __shared__ int    si[512];
    __shared__ double sS2;
    __shared__ ull    sK;

    const int b = blockIdx.x;
    const int t = threadIdx.x;
    const int bcnt = g_bcnt[b];
    const double cm2 = g_cm2[b];
    const int cab = g_cab[b];
    const float p2f = topps2[b];

    ull keys[16];
#pragma unroll
    for (int i = 0; i < 16; i++) {
        int r = t * 16 + i;
        keys[i] = (r < bcnt) ? g_b2buf[(size_t)b * HCAP + r] : ~0ull;
    }
    Sorter512(*(Sorter512::TempStorage*)dynsm).Sort(keys, 0, 48);
    __syncthreads();

    // exclusive base of double prefix over sorted p
    double loc = 0.0;
#pragma unroll
    for (int i = 0; i < 16; i++) {
        int r = t * 16 + i;
        if (r < bcnt) loc += (double)key_p(keys[i]);
    }
    sd[t] = loc;
    __syncthreads();
    for (int o = 1; o < 512; o <<= 1) {
        double v = (t >= o) ? sd[t - o] : 0.0;
        __syncthreads();
        sd[t] += v;
        __syncthreads();
    }
    const double base = (t > 0) ? sd[t - 1] : 0.0;

    // walk: first rank failing f32 test  (cs - ps > p2)
    int ff = INT_MAX;
    {
        double cum = cm2 + base;
#pragma unroll
        for (int i = 0; i < 16; i++) {
            int r = t * 16 + i;
            if (r < bcnt) {
                float p = key_p(keys[i]);
                cum += (double)p;
                float cse = (float)cum;
                float exf = cse - p;
                if (exf > p2f && r < ff) ff = r;
            }
        }
    }
    si[t] = ff;
    __syncthreads();
    for (int o = 256; o > 0; o >>= 1) {
        if (t < o) si[t] = min(si[t], si[t + o]);
        __syncthreads();
    }
    const int r2in = min(si[0], bcnt);

    if (t == 0) {
        sS2 = cm2;  // r2in == 0 fallback (no bucket member)
        sK = (((ull)(0x7FFFFFFFu - (((unsigned)g_B2[b] + 1u) << 20))) << 17) | 0x1FFFFull;
    }
    __syncthreads();
    if (r2in > 0 && t == (r2in - 1) / 16) {
        double cum = cm2 + base;
#pragma unroll
        for (int i = 0; i < 16; i++) {
            int r = t * 16 + i;
            if (r < bcnt && r <= r2in - 1) {
                cum += (double)key_p(keys[i]);
                if (r == r2in - 1) { sS2 = cum; sK = keys[i]; }
            }
        }
    }
    __syncthreads();
    if (t == 0) {
        g_S2f[b] = (float)sS2;
        g_kstar[b] = sK;
    }
}

// ---------------------------------------------------------------------------
// K2a: sort head, apply top-k/top-p/min-p, inverse-CDF sample, emit
// token_ids and next_token_logprobs.
// ---------------------------------------------------------------------------
__global__ __launch_bounds__(512) void k2a_kernel(
    const int* __restrict__ topks,
    const float* __restrict__ topps,
    const float* __restrict__ minps,
    const float* __restrict__ uu,
    float* __restrict__ out) {
    extern __shared__ char dynsm[];
    __shared__ double sd[512];
    __shared__ int    si[512];
    __shared__ int    s_rf, s_s;
    __shared__ float  s_total, s_target;

    const int b = blockIdx.x;
    const int t = threadIdx.x;
    const int hcnt = g_hcnt[b];
    const float invf = g_invf[b];
    const float p1 = topps[b];
    const float thr = invf * minps[b];   // ps[0] * min_p (f32, matches ref)

    ull keys[16];
#pragma unroll
    for (int i = 0; i < 16; i++) {
        int r = t * 16 + i;
        keys[i] = (r < hcnt) ? g_head[(size_t)b * HCAP + r] : ~0ull;
    }
    Sorter512(*(Sorter512::TempStorage*)dynsm).Sort(keys, 0, 48);
    __syncthreads();

    double loc = 0.0;
#pragma unroll
    for (int i = 0; i < 16; i++) {
        int r = t * 16 + i;
        if (r < hcnt) loc += (double)key_p(keys[i]);
    }
    sd[t] = loc;
    __syncthreads();
    for (int o = 1; o < 512; o <<= 1) {
        double v = (t >= o) ? sd[t - o] : 0.0;
        __syncthreads();
        sd[t] += v;
        __syncthreads();
    }
    const double base = (t > 0) ? sd[t - 1] : 0.0;

    // counts: top-p pass count (f32 emulation), min-p pass count
    int c1 = 0, cm = 0;
    {
        double cum = base;
#pragma unroll
        for (int i = 0; i < 16; i++) {
            int r = t * 16 + i;
            if (r < hcnt) {
                float p = key_p(keys[i]);
                cum += (double)p;
                float cse = (float)cum;
                float exf = cse - p;
                c1 += !(exf > p1);
                cm += (p >= thr);
            }
        }
    }
    si[t] = c1;
    __syncthreads();
    for (int o = 256; o > 0; o >>= 1) { if (t < o) si[t] += si[t + o]; __syncthreads(); }
    const int rp1 = si[0];
    __syncthreads();
    si[t] = cm;
    __syncthreads();
    for (int o = 256; o > 0; o >>= 1) { if (t < o) si[t] += si[t + o]; __syncthreads(); }
    const int rminp = si[0];
    __syncthreads();

    if (t == 0) {
        int k = topks[b];
        if (k < 1) k = 1;
        if (k > SV) k = SV;
        int rf = min(min(k, rp1), rminp);
        if (rf < 1) rf = 1;
        if (rf > hcnt) rf = hcnt;
        s_rf = rf;
    }
    __syncthreads();
    const int rf = s_rf;

    // total = f32(cs[rf-1])  (owner thread recomputes its running cum)
    if (t == (rf - 1) / 16) {
        double cum = base;
#pragma unroll
        for (int i = 0; i < 16; i++) {
            int r = t * 16 + i;
            if (r <= rf - 1) {
                cum += (double)key_p(keys[i]);
                if (r == rf - 1) s_total = (float)cum;
            }
        }
    }
    __syncthreads();
    if (t == 0) s_target = uu[b] * s_total;
    __syncthreads();
    const float target = s_target;

    // sampled rank = #{ r < rf : f32(cs_r) < target }
    int cnt = 0;
    {
        double cum = base;
#pragma unroll
        for (int i = 0; i < 16; i++) {
            int r = t * 16 + i;
            if (r < rf) {
                cum += (double)key_p(keys[i]);
                if ((float)cum < target) cnt++;
            }
        }
    }
    si[t] = cnt;
    __syncthreads();
    for (int o = 256; o > 0; o >>= 1) { if (t < o) si[t] += si[t + o]; __syncthreads(); }
    if (t == 0) {
        int ss = si[0];
        if (ss < 0) ss = 0;
        if (ss > SV - 1) ss = SV - 1;
        s_s = ss;
    }
    __syncthreads();
    const int ssel = s_s;

    if (t == ssel / 16) {
#pragma unroll
        for (int i = 0; i < 16; i++) {
            int r = t * 16 + i;
            if (r == ssel) {
                ull kk = keys[i];
                int tok = key_idx(kk);
                float psf = key_p(kk);
                float S2f = g_S2f[b];
                ull Kst = g_kstar[b];
                float nlp = (kk <= Kst) ? fmaxf(logf(psf / S2f), -FLT_MAX) : -FLT_MAX;
                out[b] = (float)tok;                               // token_ids
                out[(size_t)SB + (size_t)SB * SV + b] = nlp;       // next_token_logprobs
            }
        }
    }
}

// ---------------------------------------------------------------------------
// K3: coalesced logprob matrix: member iff key48 <= Kstar.
// ---------------------------------------------------------------------------
__global__ void k3_kernel(float* __restrict__ out) {
    const int b = blockIdx.y;
    const int i = blockIdx.x * blockDim.x + threadIdx.x;
    const float invf = g_invf[b];
    const float S2f = g_S2f[b];
    const ull Kst = g_kstar[b];
    const float e = g_work[(size_t)b * SV + i];
    const float p = e * invf;
    const ull key = make_key(__float_as_uint(p), i);
    float val = -FLT_MAX;
    if (key <= Kst) val = fmaxf(logf(p / S2f), -FLT_MAX);
    out[(size_t)SB + (size_t)b * SV + i] = val;
}

// ---------------------------------------------------------------------------
// Host launcher (graph-capturable: kernel launches only)
// ---------------------------------------------------------------------------
extern "C" void kernel_launch(void* const* d_in, const int* in_sizes, int n_in,
                              void* d_out, int out_size) {
    const float* logits = (const float*)d_in[0];
    const float* temps  = (const float*)d_in[1];
    const int*   topks  = (const int*)d_in[2];
    const float* topps  = (const float*)d_in[3];
    const float* topps2 = (const float*)d_in[4];
    const float* minps  = (const float*)d_in[5];
    const float* u      = (const float*)d_in[6];
    float* out = (float*)d_out;

    const int sortBytes = (int)sizeof(Sorter512::TempStorage);
    cudaFuncSetAttribute(k2b_kernel, cudaFuncAttributeMaxDynamicSharedMemorySize, sortBytes);
    cudaFuncSetAttribute(k2a_kernel, cudaFuncAttributeMaxDynamicSharedMemorySize, sortBytes);

    k1_kernel<<<SB, 1024>>>(logits, temps, topps2);
    k2b_kernel<<<SB, 512, sortBytes>>>(topps2);
    k2a_kernel<<<SB, 512, sortBytes>>>(topks, topps, minps, u, out);
    dim3 g3(SV / 256, SB);
    k3_kernel<<<g3, 256>>>(out);
}

// round 7
// speedup vs baseline: 4.0589x; 1.4419x over previous
#include <cuda_runtime.h>
#include <cub/block/block_radix_sort.cuh>
#include <math.h>
#include <float.h>
#include <limits.h>
#include <stdint.h>

#define SB 128
#define SV 128000
#define SQ (SV / 4)        // 32000 float4 per row
#define HCAP 8192          // per-row gather capacity
#define HEADN 2048         // head size needed (top_ks <= 2047)
typedef unsigned long long ull;

// ---------------------------------------------------------------------------
// Static device scratch
// ---------------------------------------------------------------------------
__device__ float    g_work[(size_t)SB * SV];        // e = exp(x - M), 65.5 MB
__device__ ull      g_histpart[(size_t)SB * 8 * 1024];  // per-block hist partials, 8 MB
__device__ ull      g_head[(size_t)SB * HCAP];
__device__ ull      g_b2buf[(size_t)SB * HCAP];
__device__ unsigned g_maxbits[SB];
__device__ float    g_invf[SB];                     // (float)(1/S)  == ps[0]
__device__ double   g_cm2[SB];                      // p-mass strictly above crossing bucket
__device__ int      g_Bk[SB];                       // head threshold e-bucket
__device__ int      g_B2[SB];                       // crossing e-bucket
__device__ int      g_hcnt[SB];
__device__ int      g_bcnt[SB];
__device__ float    g_S2f[SB];                      // nucleus mass (f32)
__device__ ull      g_kstar[SB];                    // largest member key
__device__ ull      g_sampkey[SB];                  // sampled element's key

// key48: ascending == p descending, index ascending (stable argsort ties)
__device__ __forceinline__ ull make_key(unsigned pb, int idx) {
    return (((ull)(0x7FFFFFFFu - pb)) << 17) | (unsigned)idx;
}
__device__ __forceinline__ float key_p(ull k) {
    return __uint_as_float(0x7FFFFFFFu - (unsigned)(k >> 17));
}
__device__ __forceinline__ int key_idx(ull k) { return (int)(k & 0x1FFFFull); }

// monotone uint mapping for float atomicMax
__device__ __forceinline__ unsigned fmap(float f) {
    unsigned b = __float_as_uint(f);
    return (b & 0x80000000u) ? ~b : (b | 0x80000000u);
}
__device__ __forceinline__ float funmap(unsigned m) {
    unsigned b = (m & 0x80000000u) ? (m & 0x7FFFFFFFu) : ~m;
    return __uint_as_float(b);
}

// warp-aggregated filtered append (all lanes must call)
__device__ __forceinline__ void wagg_append(bool pred, ull key, int* cnt, ull* buf) {
    unsigned m = __ballot_sync(0xFFFFFFFFu, pred);
    if (m == 0) return;
    const int lane = threadIdx.x & 31;
    const int leader = __ffs(m) - 1;
    int pos0 = 0;
    if (lane == leader) pos0 = atomicAdd(cnt, __popc(m));
    pos0 = __shfl_sync(0xFFFFFFFFu, pos0, leader);
    if (pred) {
        int pos = pos0 + __popc(m & ((1u << lane) - 1u));
        if (pos < HCAP) buf[pos] = key;
    }
}

// ---------------------------------------------------------------------------
// K_init: reset per-launch state (graph-replay safe)
// ---------------------------------------------------------------------------
__global__ void k_init() {
    const int t = threadIdx.x;
    if (t < SB) { g_maxbits[t] = 0u; g_hcnt[t] = 0; g_bcnt[t] = 0; }
}

// ---------------------------------------------------------------------------
// K_max: per-row max of RAW logits (division is monotone, so M = f32(Lmax/T))
// grid (8, SB) x 512
// ---------------------------------------------------------------------------
__global__ __launch_bounds__(512) void k_max(const float* __restrict__ logits) {
    __shared__ float sf[512];
    const int b = blockIdx.y;
    const float4* row = (const float4*)(logits + (size_t)b * SV);
    float m = -FLT_MAX;
#pragma unroll
    for (int j = 0; j < 8; j++) {
        int q = j * 4096 + blockIdx.x * 512 + threadIdx.x;
        if (q < SQ) {
            float4 v = row[q];
            m = fmaxf(m, fmaxf(fmaxf(v.x, v.y), fmaxf(v.z, v.w)));
        }
    }
    sf[threadIdx.x] = m;
    __syncthreads();
    for (int o = 256; o > 0; o >>= 1) {
        if (threadIdx.x < o) sf[threadIdx.x] = fmaxf(sf[threadIdx.x], sf[threadIdx.x + o]);
        __syncthreads();
    }
    if (threadIdx.x == 0) atomicMax(&g_maxbits[b], fmap(sf[0]));
}

// ---------------------------------------------------------------------------
// K_exp: e = expf(l/T - M) -> g_work, fused exact e-bit histogram (smem,
// packed count<<42 | sig24).  MUFU (expf) overlaps LSU (atomics).
// grid (8, SB) x 512
// ---------------------------------------------------------------------------
__global__ __launch_bounds__(512) void k_exp(const float* __restrict__ logits,
                                             const float* __restrict__ temps) {
    __shared__ ull hist[1024];
    hist[threadIdx.x] = 0ull;
    hist[threadIdx.x + 512] = 0ull;
    const int b = blockIdx.y;
    const float T = temps[b];
    const float M = funmap(g_maxbits[b]) / T;   // == max_i f32(l_i/T)
    const float4* row = (const float4*)(logits + (size_t)b * SV);
    float4* erow = (float4*)(g_work + (size_t)b * SV);
    __syncthreads();
#pragma unroll
    for (int j = 0; j < 8; j++) {
        int q = j * 4096 + blockIdx.x * 512 + threadIdx.x;
        if (q < SQ) {
            float4 l = row[q];
            float4 e;
            e.x = expf(l.x / T - M);
            e.y = expf(l.y / T - M);
            e.z = expf(l.z / T - M);
            e.w = expf(l.w / T - M);
            erow[q] = e;
            unsigned eb;
            eb = __float_as_uint(e.x);
            if (eb) atomicAdd(&hist[eb >> 20], (1ull << 42) | (ull)((eb & 0x7FFFFFu) | 0x800000u));
            eb = __float_as_uint(e.y);
            if (eb) atomicAdd(&hist[eb >> 20], (1ull << 42) | (ull)((eb & 0x7FFFFFu) | 0x800000u));
            eb = __float_as_uint(e.z);
            if (eb) atomicAdd(&hist[eb >> 20], (1ull << 42) | (ull)((eb & 0x7FFFFFu) | 0x800000u));
            eb = __float_as_uint(e.w);
            if (eb) atomicAdd(&hist[eb >> 20], (1ull << 42) | (ull)((eb & 0x7FFFFFu) | 0x800000u));
        }
    }
    __syncthreads();
    ull* outp = &g_histpart[((size_t)(b * 8 + blockIdx.x)) << 10];
    outp[threadIdx.x] = hist[threadIdx.x];
    outp[threadIdx.x + 512] = hist[threadIdx.x + 512];
}

// ---------------------------------------------------------------------------
// K_sel: merge hist partials; exact S; suffix scans; pick head bucket Bk and
// nucleus crossing bucket B2; cm2 (p-units) and invf.  One block per row.
// ---------------------------------------------------------------------------
__global__ __launch_bounds__(1024) void k_sel(const float* __restrict__ topps2) {
    __shared__ int    sh_i[1024];
    __shared__ double sh_d[1024];
    __shared__ double sS, s_cm2;
    __shared__ int    s_B2, s_minb, s_Bk;
    const int b = blockIdx.x;
    const int t = threadIdx.x;
    if (t == 0) { s_B2 = -1; s_minb = 1024; s_Bk = 0; }

    ull h = 0ull;
#pragma unroll
    for (int j = 0; j < 8; j++) h += g_histpart[(((size_t)(b * 8 + j)) << 10) + t];
    const int cnt = (int)(h >> 42);
    const double mass = ldexp((double)(h & ((1ull << 42) - 1ull)), (t >> 3) - 150);

    sh_i[t] = cnt; sh_d[t] = mass;
    __syncthreads();
    // suffix (descending-p == ascending-bucket-index-from-top) inclusive scans
    for (int o = 1; o < 1024; o <<= 1) {
        int iv = 0; double dv = 0.0;
        if (t + o < 1024) { iv = sh_i[t + o]; dv = sh_d[t + o]; }
        __syncthreads();
        sh_i[t] += iv; sh_d[t] += dv;
        __syncthreads();
    }
    if (t == 0) sS = sh_d[0];
    __syncthreads();
    const double S = sS;
    const double p2S = (double)topps2[b] * S;
    const int    ccincl = sh_i[t];
    const double cmincl = sh_d[t];
    const int    ccnext = (t < 1023) ? sh_i[t + 1] : 0;
    const double cmnext = (t < 1023) ? sh_d[t + 1] : 0.0;

    if (ccincl >= HEADN && ccnext < HEADN) s_Bk = t;
    if (cnt > 0) {
        atomicMin(&s_minb, t);
        if (cmnext <= p2S && cmincl > p2S) { s_B2 = t; s_cm2 = cmnext; }
    }
    __syncthreads();
    if (s_B2 < 0 && t == s_minb) { s_B2 = t; s_cm2 = cmnext; }
    __syncthreads();
    if (t == 0) {
        g_Bk[b] = s_Bk;
        g_B2[b] = s_B2;
        g_cm2[b] = s_cm2 / S;           // p-units mass strictly above bucket
        g_invf[b] = (float)(1.0 / S);
    }
}

// ---------------------------------------------------------------------------
// K_gather: append head candidates (e-bits >= Bk<<20) and crossing-bucket
// elements, as p-space keys.  Warp-aggregated atomics.  grid (8, SB) x 512
// ---------------------------------------------------------------------------
__global__ __launch_bounds__(512) void k_gather() {
    const int b = blockIdx.y;
    const unsigned thk  = ((unsigned)g_Bk[b]) << 20;
    const unsigned b2lo = ((unsigned)g_B2[b]) << 20;
    const unsigned b2hi = b2lo + (1u << 20);
    const float invf = g_invf[b];
    const float4* erow = (const float4*)(g_work + (size_t)b * SV);
    ull* hb = &g_head[(size_t)b * HCAP];
    ull* bb = &g_b2buf[(size_t)b * HCAP];
#pragma unroll
    for (int j = 0; j < 8; j++) {
        int q = j * 4096 + blockIdx.x * 512 + threadIdx.x;
        bool valid = (q < SQ);
        float4 e = valid ? erow[q] : make_float4(0.f, 0.f, 0.f, 0.f);
        float ev[4] = {e.x, e.y, e.z, e.w};
#pragma unroll
        for (int c = 0; c < 4; c++) {
            unsigned eb = __float_as_uint(ev[c]);
            bool hh = valid && (eb >= thk);
            bool b2 = valid && (eb >= b2lo) && (eb < b2hi);
            ull key = 0ull;
            if (hh || b2) {
                float p = ev[c] * invf;
                key = make_key(__float_as_uint(p), q * 4 + c);
            }
            wagg_append(hh, key, &g_hcnt[b], hb);
            wagg_append(b2, key, &g_bcnt[b], bb);
        }
    }
}

// ---------------------------------------------------------------------------
// K2 merged: 256 blocks.  blocks [0,128): nucleus boundary (was k2b);
// blocks [128,256): head sort + sampling (was k2a, nlp deferred to k3).
// ---------------------------------------------------------------------------
typedef cub::BlockRadixSort<ull, 512, 16> Sorter512;

__global__ __launch_bounds__(512) void k2_kernel(
    const float* __restrict__ topps2,
    const int* __restrict__ topks,
    const float* __restrict__ topps,
    const float* __restrict__ minps,
    const float* __restrict__ uu,
    float* __restrict__ out) {
    extern __shared__ char dynsm[];
    __shared__ double sd[512];
    __shared__ int    si[512];
    __shared__ double sS2;
    __shared__ ull    sK;
    __shared__ int    s_rf, s_s;
    __shared__ float  s_total, s_target;

    const int t = threadIdx.x;
    const int role = blockIdx.x >> 7;      // 0 = nucleus, 1 = sampling
    const int b = blockIdx.x & 127;

    if (role == 0) {
        // ---------------- nucleus boundary (k2b) ----------------
        const int bcnt = min(g_bcnt[b], HCAP);
        const double cm2 = g_cm2[b];
        const float p2f = topps2[b];

        ull keys[16];
#pragma unroll
        for (int i = 0; i < 16; i++) {
            int r = t * 16 + i;
            keys[i] = (r < bcnt) ? g_b2buf[(size_t)b * HCAP + r] : ~0ull;
        }
        Sorter512(*(Sorter512::TempStorage*)dynsm).Sort(keys, 0, 48);
        __syncthreads();

        double loc = 0.0;
#pragma unroll
        for (int i = 0; i < 16; i++) {
            int r = t * 16 + i;
            if (r < bcnt) loc += (double)key_p(keys[i]);
        }
        sd[t] = loc;
        __syncthreads();
        for (int o = 1; o < 512; o <<= 1) {
            double v = (t >= o) ? sd[t - o] : 0.0;
            __syncthreads();
            sd[t] += v;
            __syncthreads();
        }
        const double base = (t > 0) ? sd[t - 1] : 0.0;

        int ff = INT_MAX;
        {
            double cum = cm2 + base;
#pragma unroll
            for (int i = 0; i < 16; i++) {
                int r = t * 16 + i;
                if (r < bcnt) {
                    float p = key_p(keys[i]);
                    cum += (double)p;
                    float cse = (float)cum;
                    if (cse - p > p2f && r < ff) ff = r;
                }
            }
        }
        si[t] = ff;
        __syncthreads();
        for (int o = 256; o > 0; o >>= 1) {
            if (t < o) si[t] = min(si[t], si[t + o]);
            __syncthreads();
        }
        const int r2in = min(si[0], bcnt);

        if (t == 0) {
            sS2 = cm2;                 // r2in == 0: members are above-bucket only
            sK = keys[0] - 1ull;       // strictly below smallest bucket key
        }
        __syncthreads();
        if (r2in > 0 && t == (r2in - 1) / 16) {
            double cum = cm2 + base;
#pragma unroll
            for (int i = 0; i < 16; i++) {
                int r = t * 16 + i;
                if (r < bcnt && r <= r2in - 1) {
                    cum += (double)key_p(keys[i]);
                    if (r == r2in - 1) { sS2 = cum; sK = keys[i]; }
                }
            }
        }
        __syncthreads();
        if (t == 0) {
            g_S2f[b] = (float)sS2;
            g_kstar[b] = sK;
        }
    } else {
        // ---------------- head sort + sampling (k2a) ----------------
        const int hcnt = min(g_hcnt[b], HCAP);
        const float invf = g_invf[b];
        const float p1 = topps[b];
        const float thr = invf * minps[b];   // ps[0] * min_p

        ull keys[16];
#pragma unroll
        for (int i = 0; i < 16; i++) {
            int r = t * 16 + i;
            keys[i] = (r < hcnt) ? g_head[(size_t)b * HCAP + r] : ~0ull;
        }
        Sorter512(*(Sorter512::TempStorage*)dynsm).Sort(keys, 0, 48);
        __syncthreads();

        double loc = 0.0;
#pragma unroll
        for (int i = 0; i < 16; i++) {
            int r = t * 16 + i;
            if (r < hcnt) loc += (double)key_p(keys[i]);
        }
        sd[t] = loc;
        __syncthreads();
        for (int o = 1; o < 512; o <<= 1) {
            double v = (t >= o) ? sd[t - o] : 0.0;
            __syncthreads();
            sd[t] += v;
            __syncthreads();
        }
        const double base = (t > 0) ? sd[t - 1] : 0.0;

        int c1 = 0, cm = 0;
        {
            double cum = base;
#pragma unroll
            for (int i = 0; i < 16; i++) {
                int r = t * 16 + i;
                if (r < hcnt) {
                    float p = key_p(keys[i]);
                    cum += (double)p;
                    float cse = (float)cum;
                    c1 += !((cse - p) > p1);
                    cm += (p >= thr);
                }
            }
        }
        si[t] = c1;
        __syncthreads();
        for (int o = 256; o > 0; o >>= 1) { if (t < o) si[t] += si[t + o]; __syncthreads(); }
        const int rp1 = si[0];
        __syncthreads();
        si[t] = cm;
        __syncthreads();
        for (int o = 256; o > 0; o >>= 1) { if (t < o) si[t] += si[t + o]; __syncthreads(); }
        const int rminp = si[0];
        __syncthreads();

        if (t == 0) {
            int k = topks[b];
            if (k < 1) k = 1;
            if (k > SV) k = SV;
            int rf = min(min(k, rp1), rminp);
            if (rf < 1) rf = 1;
            if (rf > hcnt) rf = hcnt;
            s_rf = rf;
        }
        __syncthreads();
        const int rf = s_rf;

        if (t == (rf - 1) / 16) {
            double cum = base;
#pragma unroll
            for (int i = 0; i < 16; i++) {
                int r = t * 16 + i;
                if (r <= rf - 1) {
                    cum += (double)key_p(keys[i]);
                    if (r == rf - 1) s_total = (float)cum;
                }
            }
        }
        __syncthreads();
        if (t == 0) s_target = uu[b] * s_total;
        __syncthreads();
        const float target = s_target;

        int cnt2 = 0;
        {
            double cum = base;
#pragma unroll
            for (int i = 0; i < 16; i++) {
                int r = t * 16 + i;
                if (r < rf) {
                    cum += (double)key_p(keys[i]);
                    if ((float)cum < target) cnt2++;
                }
            }
        }
        si[t] = cnt2;
        __syncthreads();
        for (int o = 256; o > 0; o >>= 1) { if (t < o) si[t] += si[t + o]; __syncthreads(); }
        if (t == 0) {
            int ss = si[0];
            if (ss < 0) ss = 0;
            if (ss > SV - 1) ss = SV - 1;
            s_s = ss;
        }
        __syncthreads();
        const int ssel = s_s;

        if (t == ssel / 16) {
#pragma unroll
            for (int i = 0; i < 16; i++) {
                int r = t * 16 + i;
                if (r == ssel) {
                    ull kk = keys[i];
                    out[b] = (float)key_idx(kk);   // token_ids
                    g_sampkey[b] = kk;             // nlp deferred to k3
                }
            }
        }
    }
}

// ---------------------------------------------------------------------------
// K3: coalesced logprob matrix (float4), member iff key <= Kstar.
// Also writes next_token_logprobs (one thread per row).
// grid (125, SB) x 256 — one float4 per thread.
// ---------------------------------------------------------------------------
__global__ __launch_bounds__(256) void k3_kernel(float* __restrict__ out) {
    const int b = blockIdx.y;
    const int q = blockIdx.x * 256 + threadIdx.x;   // 0..31999
    const float invf = g_invf[b];
    const float S2f = g_S2f[b];
    const ull Kst = g_kstar[b];
    const unsigned khi = (unsigned)(Kst >> 17);
    const unsigned klo = (unsigned)(Kst & 0x1FFFFull);

    const float4 e = ((const float4*)(g_work + (size_t)b * SV))[q];
    float ev[4] = {e.x, e.y, e.z, e.w};
    float ov[4];
#pragma unroll
    for (int c = 0; c < 4; c++) {
        float p = ev[c] * invf;
        unsigned pk = 0x7FFFFFFFu - __float_as_uint(p);
        bool mem = (pk < khi) || (pk == khi && (unsigned)(q * 4 + c) <= klo);
        ov[c] = mem ? fmaxf(logf(p / S2f), -FLT_MAX) : -FLT_MAX;
    }
    ((float4*)(out + (size_t)SB + (size_t)b * SV))[q] =
        make_float4(ov[0], ov[1], ov[2], ov[3]);

    if (q == 0) {
        ull kk = g_sampkey[b];
        float psf = key_p(kk);
        float nlp = (kk <= Kst) ? fmaxf(logf(psf / S2f), -FLT_MAX) : -FLT_MAX;
        out[(size_t)SB + (size_t)SB * SV + b] = nlp;
    }
}

// ---------------------------------------------------------------------------
// Host launcher (graph-capturable: kernel launches only)
// ---------------------------------------------------------------------------
extern "C" void kernel_launch(void* const* d_in, const int* in_sizes, int n_in,
                              void* d_out, int out_size) {
    const float* logits = (const float*)d_in[0];
    const float* temps  = (const float*)d_in[1];
    const int*   topks  = (const int*)d_in[2];
    const float* topps  = (const float*)d_in[3];
    const float* topps2 = (const float*)d_in[4];
    const float* minps  = (const float*)d_in[5];
    const float* u      = (const float*)d_in[6];
    float* out = (float*)d_out;

    const int sortBytes = (int)sizeof(Sorter512::TempStorage);
    cudaFuncSetAttribute(k2_kernel, cudaFuncAttributeMaxDynamicSharedMemorySize, sortBytes);

    k_init<<<1, SB>>>();
    {
        dim3 g(8, SB);
        k_max<<<g, 512>>>(logits);
        k_exp<<<g, 512>>>(logits, temps);
    }
    k_sel<<<SB, 1024>>>(topps2);
    {
        dim3 g(8, SB);
        k_gather<<<g, 512>>>();
    }
    k2_kernel<<<256, 512, sortBytes>>>(topps2, topks, topps, minps, u, out);
    {
        dim3 g(SQ / 256, SB);
        k3_kernel<<<g, 256>>>(out);
    }
}